// round 8
// baseline (speedup 1.0000x reference)
#include <cuda_runtime.h>
#include <cuda_bf16.h>
#include <mma.h>
#include <float.h>
#include <math.h>
#include <stdint.h>

#define NCH 65536
#define BB  64
#define LL  512
#define MS  8
#define HID 128

__device__ float g_kproj[(size_t)BB * LL * MS * HID];   // 134 MB scratch
__device__ float g_qproj[(size_t)NCH * HID];            // 33 MB
__device__ int   g_selidx[(size_t)NCH * MS];
__device__ int   g_seln[NCH];
// pre-split bf16 hi/lo operands
__device__ __nv_bfloat16 g_khi[(size_t)BB * LL * 64];
__device__ __nv_bfloat16 g_klo[(size_t)BB * LL * 64];
__device__ __nv_bfloat16 g_qhi[(size_t)NCH * 64];
__device__ __nv_bfloat16 g_qlo[(size_t)NCH * 64];
__device__ __nv_bfloat16 g_w1hi[577 * 128];
__device__ __nv_bfloat16 g_w1lo[577 * 128];

using namespace nvcuda;

// order-preserving float->u32 (monotonic); masked entries use 0
__device__ __forceinline__ unsigned f2u(float f) {
    unsigned u = __float_as_uint(f);
    return (u & 0x80000000u) ? ~u : (u | 0x80000000u);
}

__device__ __forceinline__ void split4(const float* __restrict__ src,
                                       __nv_bfloat16* __restrict__ dh,
                                       __nv_bfloat16* __restrict__ dl, int i)
{
    float4 v = reinterpret_cast<const float4*>(src)[i];
    float f[4] = {v.x, v.y, v.z, v.w};
    __nv_bfloat16 h[4], l[4];
#pragma unroll
    for (int e = 0; e < 4; e++) {
        h[e] = __float2bfloat16(f[e]);
        l[e] = __float2bfloat16(f[e] - __bfloat162float(h[e]));
    }
    __nv_bfloat162 h01; h01.x = h[0]; h01.y = h[1];
    __nv_bfloat162 h23; h23.x = h[2]; h23.y = h[3];
    __nv_bfloat162 l01; l01.x = l[0]; l01.y = l[1];
    __nv_bfloat162 l23; l23.x = l[2]; l23.y = l[3];
    reinterpret_cast<__nv_bfloat162*>(dh)[i * 2]     = h01;
    reinterpret_cast<__nv_bfloat162*>(dh)[i * 2 + 1] = h23;
    reinterpret_cast<__nv_bfloat162*>(dl)[i * 2]     = l01;
    reinterpret_cast<__nv_bfloat162*>(dl)[i * 2 + 1] = l23;
}

// ---------------------------------------------------------------------------
// Split kernel: k, q, W1 -> bf16 hi/lo
// ---------------------------------------------------------------------------
__global__ void split_kernel(const float* __restrict__ kmat,
                             const float* __restrict__ q,
                             const float* __restrict__ W1)
{
    const int stride = gridDim.x * blockDim.x;
    const int t = blockIdx.x * blockDim.x + threadIdx.x;
    for (int i = t; i < (BB * LL * 64) / 4; i += stride)
        split4(kmat, g_khi, g_klo, i);
    for (int i = t; i < (NCH * 64) / 4; i += stride)
        split4(q, g_qhi, g_qlo, i);
    for (int i = t; i < (577 * 128) / 4; i += stride)
        split4(W1, g_w1hi, g_w1lo, i);
}

// ---------------------------------------------------------------------------
// Mega kernel: heterogeneous grid, 4608 CTAs of 256 threads.
//   bx%9 < 4  -> selection CTA (2048 total; warp = 4 chains)
//   bx%9 >= 4 -> WMMA GEMM CTA (2560 total: 2048 kproj + 512 qproj)
// ---------------------------------------------------------------------------
#define A_LD 72
#define B_LD 136
#define OFF_AH 0
#define OFF_AL 18432
#define OFF_BH 36864
#define OFF_BL 54272
#define KP_SMEM 71680
#define STG_LD  132

__global__ __launch_bounds__(256, 2) void mega_kernel(
    const int* __restrict__ mask, const float* __restrict__ rank)
{
    extern __shared__ char smem[];
    const int bx  = blockIdx.x;
    const int tid = threadIdx.x;
    const int group = bx / 9, rr9 = bx % 9;

    if (rr9 < 4) {
        // ================= selection path =================================
        const int sidx = group * 4 + rr9;            // 0..2047
        const int w = tid >> 5, lane = tid & 31;
        const unsigned full = 0xffffffffu;

        for (int cc = 0; cc < 4; cc++) {
            const int chain = (sidx * 8 + w) * 4 + cc;
            const float* sc = rank + (size_t)chain * 512 + lane * 16;
            const int4*  mk = reinterpret_cast<const int4*>(
                                  mask + (size_t)chain * 512) + lane * 4;
            unsigned key[16];
            unsigned m1 = 0, m2 = 0, m3 = 0;
            int p1 = 0, p2 = 0, p3 = 0;
            int cnt = 0;
#pragma unroll
            for (int g = 0; g < 4; g++) {
                int4   mw = mk[g];
                float4 s  = *reinterpret_cast<const float4*>(sc + g * 4);
                int   me[4] = {mw.x, mw.y, mw.z, mw.w};
                float vv[4] = {s.x, s.y, s.z, s.w};
#pragma unroll
                for (int e = 0; e < 4; e++) {
                    const int i = g * 4 + e;
                    bool mm = (me[e] != 0);
                    unsigned k = mm ? f2u(vv[e]) : 0u;
                    key[i] = k;
                    cnt += mm ? 1 : 0;
                    bool g1 = k > m1, g2 = k > m2, g3 = k > m3;
                    m3 = g3 ? (g2 ? m2 : k) : m3;  p3 = g3 ? (g2 ? p2 : i) : p3;
                    m2 = g2 ? (g1 ? m1 : k) : m2;  p2 = g2 ? (g1 ? p1 : i) : p2;
                    m1 = g1 ? k : m1;              p1 = g1 ? i : p1;
                }
            }
            int tot  = __reduce_add_sync(full, cnt);
            int nsel = tot < 8 ? tot : 8;

            unsigned cons = 0;
#pragma unroll
            for (int t = 0; t < 8; t++) {
                unsigned m = __reduce_max_sync(full, m1);
                unsigned bal = __ballot_sync(full, m1 == m);
                int src = __ffs(bal) - 1;
                if (m != 0u && lane == src) {
                    cons |= 1u << p1;
                    m1 = m2; p1 = p2; m2 = m3; p2 = p3; m3 = 0; p3 = 0;
                    if (m1 == 0u) {   // rare rescan
#pragma unroll
                        for (int i = 0; i < 16; i++) {
                            unsigned k = ((cons >> i) & 1u) ? 0u : key[i];
                            bool g1 = k > m1, g2 = k > m2, g3 = k > m3;
                            m3 = g3 ? (g2 ? m2 : k) : m3;  p3 = g3 ? (g2 ? p2 : i) : p3;
                            m2 = g2 ? (g1 ? m1 : k) : m2;  p2 = g2 ? (g1 ? p1 : i) : p2;
                            m1 = g1 ? k : m1;              p1 = g1 ? i : p1;
                        }
                    }
                }
            }

            int my = __popc(cons);
            int pre = my;
#pragma unroll
            for (int off = 1; off < 32; off <<= 1) {
                int v = __shfl_up_sync(full, pre, off);
                if (lane >= off) pre += v;
            }
            pre -= my;
            if (lane == 0) g_seln[chain] = nsel;
            unsigned c = cons;
            int s = pre;
            while (c) {
                int i = __ffs(c) - 1;
                c &= c - 1;
                g_selidx[(size_t)chain * 8 + s] = lane * 16 + i;
                s++;
            }
        }
        return;
    }

    // ================= GEMM path (kproj or qproj) =========================
    __nv_bfloat16* Ah = reinterpret_cast<__nv_bfloat16*>(smem + OFF_AH);
    __nv_bfloat16* Al = reinterpret_cast<__nv_bfloat16*>(smem + OFF_AL);
    __nv_bfloat16* Bh = reinterpret_cast<__nv_bfloat16*>(smem + OFF_BH);
    __nv_bfloat16* Bl = reinterpret_cast<__nv_bfloat16*>(smem + OFF_BL);

    const int gidx = group * 5 + (rr9 - 4);          // 0..2559
    const bool isq = (gidx >= 2048);
    int m0, brow, j = 0;
    const __nv_bfloat16 *Ahg, *Alg;
    if (isq) {
        m0 = (gidx - 2048) * 128; brow = 0;
        Ahg = g_qhi; Alg = g_qlo;
    } else {
        m0 = (gidx >> 3) * 128; j = gidx & 7; brow = 64 + j * 64;
        Ahg = g_khi; Alg = g_klo;
    }

    for (int idx = tid; idx < 1024; idx += 256) {
        int r = idx >> 3, c8 = idx & 7;
        size_t src = (size_t)(m0 + r) * 64 + c8 * 8;
        *reinterpret_cast<uint4*>(Ah + r * A_LD + c8 * 8) =
            *reinterpret_cast<const uint4*>(Ahg + src);
        *reinterpret_cast<uint4*>(Al + r * A_LD + c8 * 8) =
            *reinterpret_cast<const uint4*>(Alg + src);
    }
    for (int idx = tid; idx < 1024; idx += 256) {
        int r = idx >> 4, c8 = idx & 15;
        size_t src = (size_t)(brow + r) * 128 + c8 * 8;
        *reinterpret_cast<uint4*>(Bh + r * B_LD + c8 * 8) =
            *reinterpret_cast<const uint4*>(g_w1hi + src);
        *reinterpret_cast<uint4*>(Bl + r * B_LD + c8 * 8) =
            *reinterpret_cast<const uint4*>(g_w1lo + src);
    }
    __syncthreads();

    const int w  = tid >> 5;
    const int wm = w >> 1, wn = w & 1;

    wmma::fragment<wmma::accumulator, 16, 16, 16, float> acc[2][4];
#pragma unroll
    for (int i = 0; i < 2; i++)
#pragma unroll
        for (int jn = 0; jn < 4; jn++) wmma::fill_fragment(acc[i][jn], 0.f);

#pragma unroll
    for (int k0 = 0; k0 < 64; k0 += 16) {
        wmma::fragment<wmma::matrix_a, 16, 16, 16, __nv_bfloat16,
                       wmma::row_major> fah[2], fal[2];
#pragma unroll
        for (int i = 0; i < 2; i++) {
            int ab = (wm * 32 + i * 16) * A_LD + k0;
            wmma::load_matrix_sync(fah[i], Ah + ab, A_LD);
            wmma::load_matrix_sync(fal[i], Al + ab, A_LD);
        }
#pragma unroll
        for (int jn = 0; jn < 4; jn++) {
            wmma::fragment<wmma::matrix_b, 16, 16, 16, __nv_bfloat16,
                           wmma::row_major> fbh, fbl;
            int bb = k0 * B_LD + wn * 64 + jn * 16;
            wmma::load_matrix_sync(fbh, Bh + bb, B_LD);
            wmma::load_matrix_sync(fbl, Bl + bb, B_LD);
#pragma unroll
            for (int i = 0; i < 2; i++) {
                wmma::mma_sync(acc[i][jn], fah[i], fbh, acc[i][jn]);
                wmma::mma_sync(acc[i][jn], fah[i], fbl, acc[i][jn]);
                wmma::mma_sync(acc[i][jn], fal[i], fbh, acc[i][jn]);
            }
        }
    }

    __syncthreads();
    float* so = reinterpret_cast<float*>(smem);
#pragma unroll
    for (int i = 0; i < 2; i++)
#pragma unroll
        for (int jn = 0; jn < 4; jn++)
            wmma::store_matrix_sync(
                so + (wm * 32 + i * 16) * STG_LD + wn * 64 + jn * 16,
                acc[i][jn], STG_LD, wmma::mem_row_major);
    __syncthreads();

    if (isq) {
        for (int idx = tid; idx < 4096; idx += 256) {
            int r = idx >> 5, c4 = idx & 31;
            float4 v = *reinterpret_cast<const float4*>(so + r * STG_LD + c4 * 4);
            *reinterpret_cast<float4*>(
                g_qproj + (size_t)(m0 + r) * 128 + c4 * 4) = v;
        }
    } else {
        for (int idx = tid; idx < 4096; idx += 256) {
            int r = idx >> 5, c4 = idx & 31;
            float4 v = *reinterpret_cast<const float4*>(so + r * STG_LD + c4 * 4);
            *reinterpret_cast<float4*>(
                g_kproj + (((size_t)(m0 + r)) * 8 + j) * 128 + c4 * 4) = v;
        }
    }
}

// ---------------------------------------------------------------------------
// Kernel 2 (lite): qproj load + kproj gather + bias/logc + gelu + dot W2.
// ---------------------------------------------------------------------------
__global__ __launch_bounds__(256) void chain_kernel(
    const int*   __restrict__ batch_idx,
    const int*   __restrict__ count,
    const float* __restrict__ W1,
    const float* __restrict__ b1,
    const float* __restrict__ W2,
    const float* __restrict__ b2,
    float* __restrict__ out)
{
    __shared__ float sW1last[128], sB1[128], sW2[128];
    __shared__ int   sIdx[64][8];
    __shared__ int   sN[64], sBatch[64];
    __shared__ float sLogc[64];

    const int tid = threadIdx.x;
    const int c0  = blockIdx.x * 64;

    if (tid < 128) {
        sW1last[tid] = W1[576 * 128 + tid];
        sB1[tid]     = b1[tid];
        sW2[tid]     = W2[tid];
    }
    if (tid < 64) {
        sBatch[tid] = batch_idx[c0 + tid];
        sLogc[tid]  = log1pf((float)count[c0 + tid]);
        sN[tid]     = g_seln[c0 + tid];
    }
    {
        int f = tid;
        sIdx[f >> 2][(f & 3) * 2]     = g_selidx[(size_t)c0 * 8 + f * 2];
        sIdx[f >> 2][(f & 3) * 2 + 1] = g_selidx[(size_t)c0 * 8 + f * 2 + 1];
    }
    __syncthreads();

    const int tr = tid >> 4, tc = tid & 15;

    float wl[8], bb1[8], w2[8];
#pragma unroll
    for (int u = 0; u < 8; u++) {
        wl[u]  = sW1last[tc * 8 + u];
        bb1[u] = sB1[tc * 8 + u];
        w2[u]  = sW2[tc * 8 + u];
    }

    float acc[4][8];
#pragma unroll
    for (int i = 0; i < 4; i++) {
        const int cl = tr * 4 + i;
        const float* qp = g_qproj + (size_t)(c0 + cl) * 128 + tc * 8;
        float4 a0 = *reinterpret_cast<const float4*>(qp);
        float4 a1 = *reinterpret_cast<const float4*>(qp + 4);
        const float lc = sLogc[cl];
        acc[i][0] = a0.x + bb1[0] + lc * wl[0];
        acc[i][1] = a0.y + bb1[1] + lc * wl[1];
        acc[i][2] = a0.z + bb1[2] + lc * wl[2];
        acc[i][3] = a0.w + bb1[3] + lc * wl[3];
        acc[i][4] = a1.x + bb1[4] + lc * wl[4];
        acc[i][5] = a1.y + bb1[5] + lc * wl[5];
        acc[i][6] = a1.z + bb1[6] + lc * wl[6];
        acc[i][7] = a1.w + bb1[7] + lc * wl[7];

        const int n  = sN[cl];
        const int bb = sBatch[cl];
        for (int jj = 0; jj < n; jj++) {
            size_t base = (((size_t)bb * 512 + sIdx[cl][jj]) * 8 + jj) * 128 + tc * 8;
            float4 g0 = *reinterpret_cast<const float4*>(g_kproj + base);
            float4 g1 = *reinterpret_cast<const float4*>(g_kproj + base + 4);
            acc[i][0] += g0.x; acc[i][1] += g0.y; acc[i][2] += g0.z; acc[i][3] += g0.w;
            acc[i][4] += g1.x; acc[i][5] += g1.y; acc[i][6] += g1.z; acc[i][7] += g1.w;
        }
    }

#pragma unroll
    for (int i = 0; i < 4; i++)
#pragma unroll
        for (int u = 0; u < 8; u++) {
            float x = acc[i][u];
            acc[i][u] = 0.5f * x * (1.0f + erff(x * 0.70710678118654752440f));
        }

    const float b2v = b2[0];
#pragma unroll
    for (int i = 0; i < 4; i++) {
        float p = 0.f;
#pragma unroll
        for (int u = 0; u < 8; u++) p = fmaf(acc[i][u], w2[u], p);
#pragma unroll
        for (int off = 8; off; off >>= 1)
            p += __shfl_down_sync(0xffffffffu, p, off, 16);
        if (tc == 0) out[c0 + tr * 4 + i] = p + b2v;
    }
}

// ---------------------------------------------------------------------------
extern "C" void kernel_launch(void* const* d_in, const int* in_sizes, int n_in,
                              void* d_out, int out_size)
{
    const float* q         = (const float*)d_in[0];
    const float* kmat      = (const float*)d_in[1];
    const int*   batch_idx = (const int*)d_in[2];
    const int*   mask      = (const int*)d_in[3];
    const int*   count     = (const int*)d_in[4];
    const float* rank      = (const float*)d_in[5];
    const float* W1        = (const float*)d_in[6];
    const float* b1        = (const float*)d_in[7];
    const float* W2        = (const float*)d_in[8];
    const float* b2        = (const float*)d_in[9];
    float* out = (float*)d_out;

    cudaFuncSetAttribute(mega_kernel,
                         cudaFuncAttributeMaxDynamicSharedMemorySize, KP_SMEM);

    split_kernel<<<1024, 256>>>(kmat, q, W1);
    mega_kernel<<<4608, 256, KP_SMEM>>>(mask, rank);
    chain_kernel<<<1024, 256>>>(batch_idx, count, W1, b1, W2, b2, out);
}

// round 9
// speedup vs baseline: 1.0776x; 1.0776x over previous
#include <cuda_runtime.h>
#include <cuda_bf16.h>
#include <mma.h>
#include <float.h>
#include <math.h>
#include <stdint.h>

#define NCH 65536
#define BB  64
#define LL  512
#define MS  8
#define HID 128

__device__ float g_kproj[(size_t)BB * LL * MS * HID];   // 134 MB scratch
__device__ float g_qproj[(size_t)NCH * HID];            // 33 MB
__device__ int   g_selidx[(size_t)NCH * MS];
__device__ int   g_seln[NCH];
__device__ __nv_bfloat16 g_w1hi[577 * 128];
__device__ __nv_bfloat16 g_w1lo[577 * 128];

using namespace nvcuda;

// order-preserving float->u32 (monotonic); masked entries use 0
__device__ __forceinline__ unsigned f2u(float f) {
    unsigned u = __float_as_uint(f);
    return (u & 0x80000000u) ? ~u : (u | 0x80000000u);
}

// ---------------------------------------------------------------------------
// W1 split: fp32 -> bf16 hi + lo (residual). Tiny (74K elems).
// ---------------------------------------------------------------------------
__global__ void w1split_kernel(const float* __restrict__ W1)
{
    const int n = 577 * 128;
    for (int i = blockIdx.x * blockDim.x + threadIdx.x; i < n;
         i += gridDim.x * blockDim.x) {
        float f = W1[i];
        __nv_bfloat16 h = __float2bfloat16(f);
        g_w1hi[i] = h;
        g_w1lo[i] = __float2bfloat16(f - __bfloat162float(h));
    }
}

// ---------------------------------------------------------------------------
// Kernel 0: top-8 selection. grid 2048 x 256 thr; warp = 4 chains.
// Incremental top-3 per lane + consumed-bitmask epilogue. Register-only.
// ---------------------------------------------------------------------------
__global__ __launch_bounds__(256) void select_kernel(
    const int* __restrict__ mask, const float* __restrict__ rank)
{
    const int tid = threadIdx.x;
    const int w = tid >> 5, lane = tid & 31;
    const unsigned full = 0xffffffffu;

    for (int cc = 0; cc < 4; cc++) {
        const int chain = (blockIdx.x * 8 + w) * 4 + cc;
        const float* sc = rank + (size_t)chain * 512 + lane * 16;
        const int4*  mk = reinterpret_cast<const int4*>(
                              mask + (size_t)chain * 512) + lane * 4;
        unsigned key[16];
        unsigned m1 = 0, m2 = 0, m3 = 0;
        int p1 = 0, p2 = 0, p3 = 0;
        int cnt = 0;
#pragma unroll
        for (int g = 0; g < 4; g++) {
            int4   mw = mk[g];
            float4 s  = *reinterpret_cast<const float4*>(sc + g * 4);
            int   me[4] = {mw.x, mw.y, mw.z, mw.w};
            float vv[4] = {s.x, s.y, s.z, s.w};
#pragma unroll
            for (int e = 0; e < 4; e++) {
                const int i = g * 4 + e;
                bool mm = (me[e] != 0);
                unsigned k = mm ? f2u(vv[e]) : 0u;
                key[i] = k;
                cnt += mm ? 1 : 0;
                bool g1 = k > m1, g2 = k > m2, g3 = k > m3;
                m3 = g3 ? (g2 ? m2 : k) : m3;  p3 = g3 ? (g2 ? p2 : i) : p3;
                m2 = g2 ? (g1 ? m1 : k) : m2;  p2 = g2 ? (g1 ? p1 : i) : p2;
                m1 = g1 ? k : m1;              p1 = g1 ? i : p1;
            }
        }
        int tot  = __reduce_add_sync(full, cnt);
        int nsel = tot < 8 ? tot : 8;

        unsigned cons = 0;
#pragma unroll
        for (int t = 0; t < 8; t++) {
            unsigned m = __reduce_max_sync(full, m1);
            unsigned bal = __ballot_sync(full, m1 == m);
            int src = __ffs(bal) - 1;
            if (m != 0u && lane == src) {
                cons |= 1u << p1;
                m1 = m2; p1 = p2; m2 = m3; p2 = p3; m3 = 0; p3 = 0;
                if (m1 == 0u) {   // rare rescan
#pragma unroll
                    for (int i = 0; i < 16; i++) {
                        unsigned k = ((cons >> i) & 1u) ? 0u : key[i];
                        bool g1 = k > m1, g2 = k > m2, g3 = k > m3;
                        m3 = g3 ? (g2 ? m2 : k) : m3;  p3 = g3 ? (g2 ? p2 : i) : p3;
                        m2 = g2 ? (g1 ? m1 : k) : m2;  p2 = g2 ? (g1 ? p1 : i) : p2;
                        m1 = g1 ? k : m1;              p1 = g1 ? i : p1;
                    }
                }
            }
        }

        int my = __popc(cons);
        int pre = my;
#pragma unroll
        for (int off = 1; off < 32; off <<= 1) {
            int v = __shfl_up_sync(full, pre, off);
            if (lane >= off) pre += v;
        }
        pre -= my;
        if (lane == 0) g_seln[chain] = nsel;
        unsigned c = cons;
        int s = pre;
        while (c) {
            int i = __ffs(c) - 1;
            c &= c - 1;
            g_selidx[(size_t)chain * 8 + s] = lane * 16 + i;
            s++;
        }
    }
}

// ---------------------------------------------------------------------------
// Kernel 1: kproj + qproj WMMA bf16x3. grid 2560 (2048 kproj + 512 qproj),
// 256 thr. A staged fp32->hi/lo in-kernel; epilogue stores frags DIRECTLY to
// global (no smem staging) to cut L1 traffic.
// ---------------------------------------------------------------------------
#define A_LD 72
#define B_LD 136
#define OFF_AH 0
#define OFF_AL 18432
#define OFF_BH 36864
#define OFF_BL 54272
#define KP_SMEM 71680

__global__ __launch_bounds__(256, 2) void gemm_kernel(
    const float* __restrict__ kmat, const float* __restrict__ q)
{
    extern __shared__ char smem[];
    __nv_bfloat16* Ah = reinterpret_cast<__nv_bfloat16*>(smem + OFF_AH);
    __nv_bfloat16* Al = reinterpret_cast<__nv_bfloat16*>(smem + OFF_AL);
    __nv_bfloat16* Bh = reinterpret_cast<__nv_bfloat16*>(smem + OFF_BH);
    __nv_bfloat16* Bl = reinterpret_cast<__nv_bfloat16*>(smem + OFF_BL);

    const int bx  = blockIdx.x;
    const int tid = threadIdx.x;
    const bool isq = (bx >= 2048);
    int m0, brow, j = 0;
    const float* Asrc;
    if (isq) { m0 = (bx - 2048) * 128; brow = 0; Asrc = q; }
    else     { m0 = (bx >> 3) * 128; j = bx & 7; brow = 64 + j * 64; Asrc = kmat; }

    // --- stage A: fp32 -> bf16 hi/lo during STS. 2048 float4.
    for (int idx = tid; idx < 2048; idx += 256) {
        int r = idx >> 4, c4 = idx & 15;
        float4 v = *reinterpret_cast<const float4*>(
            Asrc + (size_t)(m0 + r) * 64 + c4 * 4);
        float f[4] = {v.x, v.y, v.z, v.w};
        __nv_bfloat16 h[4], l[4];
#pragma unroll
        for (int e = 0; e < 4; e++) {
            h[e] = __float2bfloat16(f[e]);
            l[e] = __float2bfloat16(f[e] - __bfloat162float(h[e]));
        }
        __nv_bfloat162 h01; h01.x = h[0]; h01.y = h[1];
        __nv_bfloat162 h23; h23.x = h[2]; h23.y = h[3];
        __nv_bfloat162 l01; l01.x = l[0]; l01.y = l[1];
        __nv_bfloat162 l23; l23.x = l[2]; l23.y = l[3];
        __nv_bfloat162* ah = reinterpret_cast<__nv_bfloat162*>(Ah + r * A_LD + c4 * 4);
        __nv_bfloat162* al = reinterpret_cast<__nv_bfloat162*>(Al + r * A_LD + c4 * 4);
        ah[0] = h01; ah[1] = h23;
        al[0] = l01; al[1] = l23;
    }
    // --- stage B: pre-split W1 hi/lo, 1024 uint4 each
    for (int idx = tid; idx < 1024; idx += 256) {
        int r = idx >> 4, c8 = idx & 15;
        size_t src = (size_t)(brow + r) * 128 + c8 * 8;
        *reinterpret_cast<uint4*>(Bh + r * B_LD + c8 * 8) =
            *reinterpret_cast<const uint4*>(g_w1hi + src);
        *reinterpret_cast<uint4*>(Bl + r * B_LD + c8 * 8) =
            *reinterpret_cast<const uint4*>(g_w1lo + src);
    }
    __syncthreads();

    const int w  = tid >> 5;
    const int wm = w >> 1, wn = w & 1;

    wmma::fragment<wmma::accumulator, 16, 16, 16, float> acc[2][4];
#pragma unroll
    for (int i = 0; i < 2; i++)
#pragma unroll
        for (int jn = 0; jn < 4; jn++) wmma::fill_fragment(acc[i][jn], 0.f);

#pragma unroll
    for (int k0 = 0; k0 < 64; k0 += 16) {
        wmma::fragment<wmma::matrix_a, 16, 16, 16, __nv_bfloat16,
                       wmma::row_major> fah[2], fal[2];
#pragma unroll
        for (int i = 0; i < 2; i++) {
            int ab = (wm * 32 + i * 16) * A_LD + k0;
            wmma::load_matrix_sync(fah[i], Ah + ab, A_LD);
            wmma::load_matrix_sync(fal[i], Al + ab, A_LD);
        }
#pragma unroll
        for (int jn = 0; jn < 4; jn++) {
            wmma::fragment<wmma::matrix_b, 16, 16, 16, __nv_bfloat16,
                           wmma::row_major> fbh, fbl;
            int bb = k0 * B_LD + wn * 64 + jn * 16;
            wmma::load_matrix_sync(fbh, Bh + bb, B_LD);
            wmma::load_matrix_sync(fbl, Bl + bb, B_LD);
#pragma unroll
            for (int i = 0; i < 2; i++) {
                wmma::mma_sync(acc[i][jn], fah[i], fbh, acc[i][jn]);
                wmma::mma_sync(acc[i][jn], fah[i], fbl, acc[i][jn]);
                wmma::mma_sync(acc[i][jn], fal[i], fbh, acc[i][jn]);
            }
        }
    }

    // --- epilogue: store fragments directly to global (no smem staging)
    if (isq) {
#pragma unroll
        for (int i = 0; i < 2; i++)
#pragma unroll
            for (int jn = 0; jn < 4; jn++)
                wmma::store_matrix_sync(
                    g_qproj + (size_t)(m0 + wm * 32 + i * 16) * 128
                            + wn * 64 + jn * 16,
                    acc[i][jn], 128, wmma::mem_row_major);
    } else {
#pragma unroll
        for (int i = 0; i < 2; i++)
#pragma unroll
            for (int jn = 0; jn < 4; jn++)
                wmma::store_matrix_sync(
                    g_kproj + ((size_t)(m0 + wm * 32 + i * 16) * 8 + j) * 128
                            + wn * 64 + jn * 16,
                    acc[i][jn], 1024, wmma::mem_row_major);
    }
}

// ---------------------------------------------------------------------------
// Kernel 2 (lite): qproj load + kproj gather + bias/logc + gelu + dot W2.
// ---------------------------------------------------------------------------
__global__ __launch_bounds__(256) void chain_kernel(
    const int*   __restrict__ batch_idx,
    const int*   __restrict__ count,
    const float* __restrict__ W1,
    const float* __restrict__ b1,
    const float* __restrict__ W2,
    const float* __restrict__ b2,
    float* __restrict__ out)
{
    __shared__ float sW1last[128], sB1[128], sW2[128];
    __shared__ int   sIdx[64][8];
    __shared__ int   sN[64], sBatch[64];
    __shared__ float sLogc[64];

    const int tid = threadIdx.x;
    const int c0  = blockIdx.x * 64;

    if (tid < 128) {
        sW1last[tid] = W1[576 * 128 + tid];
        sB1[tid]     = b1[tid];
        sW2[tid]     = W2[tid];
    }
    if (tid < 64) {
        sBatch[tid] = batch_idx[c0 + tid];
        sLogc[tid]  = log1pf((float)count[c0 + tid]);
        sN[tid]     = g_seln[c0 + tid];
    }
    {
        int f = tid;
        sIdx[f >> 2][(f & 3) * 2]     = g_selidx[(size_t)c0 * 8 + f * 2];
        sIdx[f >> 2][(f & 3) * 2 + 1] = g_selidx[(size_t)c0 * 8 + f * 2 + 1];
    }
    __syncthreads();

    const int tr = tid >> 4, tc = tid & 15;

    float wl[8], bb1[8], w2[8];
#pragma unroll
    for (int u = 0; u < 8; u++) {
        wl[u]  = sW1last[tc * 8 + u];
        bb1[u] = sB1[tc * 8 + u];
        w2[u]  = sW2[tc * 8 + u];
    }

    float acc[4][8];
#pragma unroll
    for (int i = 0; i < 4; i++) {
        const int cl = tr * 4 + i;
        const float* qp = g_qproj + (size_t)(c0 + cl) * 128 + tc * 8;
        float4 a0 = *reinterpret_cast<const float4*>(qp);
        float4 a1 = *reinterpret_cast<const float4*>(qp + 4);
        const float lc = sLogc[cl];
        acc[i][0] = a0.x + bb1[0] + lc * wl[0];
        acc[i][1] = a0.y + bb1[1] + lc * wl[1];
        acc[i][2] = a0.z + bb1[2] + lc * wl[2];
        acc[i][3] = a0.w + bb1[3] + lc * wl[3];
        acc[i][4] = a1.x + bb1[4] + lc * wl[4];
        acc[i][5] = a1.y + bb1[5] + lc * wl[5];
        acc[i][6] = a1.z + bb1[6] + lc * wl[6];
        acc[i][7] = a1.w + bb1[7] + lc * wl[7];

        const int n  = sN[cl];
        const int bb = sBatch[cl];
        for (int jj = 0; jj < n; jj++) {
            size_t base = (((size_t)bb * 512 + sIdx[cl][jj]) * 8 + jj) * 128 + tc * 8;
            float4 g0 = *reinterpret_cast<const float4*>(g_kproj + base);
            float4 g1 = *reinterpret_cast<const float4*>(g_kproj + base + 4);
            acc[i][0] += g0.x; acc[i][1] += g0.y; acc[i][2] += g0.z; acc[i][3] += g0.w;
            acc[i][4] += g1.x; acc[i][5] += g1.y; acc[i][6] += g1.z; acc[i][7] += g1.w;
        }
    }

#pragma unroll
    for (int i = 0; i < 4; i++)
#pragma unroll
        for (int u = 0; u < 8; u++) {
            float x = acc[i][u];
            acc[i][u] = 0.5f * x * (1.0f + erff(x * 0.70710678118654752440f));
        }

    const float b2v = b2[0];
#pragma unroll
    for (int i = 0; i < 4; i++) {
        float p = 0.f;
#pragma unroll
        for (int u = 0; u < 8; u++) p = fmaf(acc[i][u], w2[u], p);
#pragma unroll
        for (int off = 8; off; off >>= 1)
            p += __shfl_down_sync(0xffffffffu, p, off, 16);
        if (tc == 0) out[c0 + tr * 4 + i] = p + b2v;
    }
}

// ---------------------------------------------------------------------------
extern "C" void kernel_launch(void* const* d_in, const int* in_sizes, int n_in,
                              void* d_out, int out_size)
{
    const float* q         = (const float*)d_in[0];
    const float* kmat      = (const float*)d_in[1];
    const int*   batch_idx = (const int*)d_in[2];
    const int*   mask      = (const int*)d_in[3];
    const int*   count     = (const int*)d_in[4];
    const float* rank      = (const float*)d_in[5];
    const float* W1        = (const float*)d_in[6];
    const float* b1        = (const float*)d_in[7];
    const float* W2        = (const float*)d_in[8];
    const float* b2        = (const float*)d_in[9];
    float* out = (float*)d_out;

    cudaFuncSetAttribute(gemm_kernel,
                         cudaFuncAttributeMaxDynamicSharedMemorySize, KP_SMEM);

    w1split_kernel<<<72, 256>>>(W1);
    select_kernel<<<2048, 256>>>(mask, rank);
    gemm_kernel<<<2560, 256, KP_SMEM>>>(kmat, q);
    chain_kernel<<<1024, 256>>>(batch_idx, count, W1, b1, W2, b2, out);
}